// round 15
// baseline (speedup 1.0000x reference)
#include <cuda_runtime.h>

// Decoder: 8 batches of 32-segment piecewise-linear functions sampled at
// 196608 uniform points. Output [8, 196608] fp32 = 6.29MB (L2-resident).
// Final form: 768 CTAs x 256 threads. Warp-0 prologue (shuffle max-scan ->
// ballot search overlapped with fast-div slope -> predicated STS publish).
// Three-way classification: 0 boundaries (~84%, 1 FFMA-imm/px), 1 boundary
// (integer-threshold select, 4 ops/px), >=2 (rare smem binary search).

#define S_TOTAL 196608
#define NB 8
#define NSEG 32
#define NP1 33
#define THREADS 256
#define ITERS 2                                     // float4s per thread
#define PIX_PER_BLOCK (THREADS * ITERS * 4)         // 2048
#define BLOCKS_PER_BATCH (S_TOTAL / PIX_PER_BLOCK)  // 96
#define FULLMASK 0xffffffffu

__global__ __launch_bounds__(THREADS) void decoder_pwl_kernel(
    const float* __restrict__ segx,
    const float* __restrict__ segy,
    float* __restrict__ out)
{
    __shared__ float4 scf[NSEG];   // fallback table {x, y, r, -} (rare blocks)
    __shared__ float4 sA;          // {c0x, c0y, c0r, -}
    __shared__ float4 sB;          // {xb(=c1x), c1y, c1r, nseg}

    const int b = blockIdx.x / BLOCKS_PER_BATCH;
    const int chunk = blockIdx.x - b * BLOCKS_PER_BATCH;
    const int tid = threadIdx.x;
    const int s_base = chunk * PIX_PER_BLOCK;
    const float inv = 1.0f / (float)S_TOTAL;        // <=1ulp vs IEEE div; tol 1e-3

    if (tid < 32) {
        const int lane = tid;
        // ---- Running-max scan over 33 knots (ties -> later entry wins) ----
        const float* px = segx + b * NP1;
        const float* py = segy + b * NP1;
        const float x0v = px[0];                     // uniform LDG, broadcast
        const float y0v = py[0];
        float xv = px[lane + 1];
        float yv = py[lane + 1];
        #pragma unroll
        for (int d = 1; d < 32; d <<= 1) {
            float ox = __shfl_up_sync(FULLMASK, xv, d);
            float oy = __shfl_up_sync(FULLMASK, yv, d);
            if (lane >= d && ox > xv) { xv = ox; yv = oy; }
        }
        if (x0v > xv) { xv = x0v; yv = y0v; }        // fold in knot 0 as prefix
        float xp = __shfl_up_sync(FULLMASK, xv, 1);  // lane l: knot X[l]
        float yp = __shfl_up_sync(FULLMASK, yv, 1);  // lane l: Y[l]
        if (lane == 0) { xp = x0v; yp = y0v; }

        // ---- Ballot search (needs only xp) — overlaps with the divide ----
        // X[] non-decreasing across lanes -> prefix mask; j = highest set bit.
        // m|1 makes mask==0 give j=0 (below-first-knot clamp); bit31 gives
        // segment 31 (above-last-knot clamp).
        const float x_lo = (float)(s_base + 1) * inv;
        const float x_hi = (float)(s_base + PIX_PER_BLOCK) * inv;
        const unsigned mlo = __ballot_sync(FULLMASK, xp <= x_lo);
        const unsigned mhi = __ballot_sync(FULLMASK, xp <= x_hi);
        const int jl = 31 - __clz(mlo | 1u);
        const int jh = 31 - __clz(mhi | 1u);

        // Slope via fast reciprocal (relerr ~2^-22, tolerance is 1e-3).
        float dd = xv - xp;
        if (dd == 0.0f) dd = 0.0001f;
        const float rs = __fdividef(yv - yp, dd);    // lane l: slope of seg l

        // Publish block record by predicated direct stores (no gathers).
        if (lane == jl) sA = make_float4(xp, yp, rs, 0.0f);
        if (lane == jh) sB = make_float4(xp, yp, rs, (float)(jh - jl));

        // Fallback table only when >=2 boundaries land in this block (<1%).
        if (jh > jl + 1) scf[lane] = make_float4(xp, yp, rs, 0.0f);
    }
    __syncthreads();

    // Address math first (independent of the LDS results below).
    float4* out4 = reinterpret_cast<float4*>(out);
    const int obase = b * (S_TOTAL / 4) + (s_base >> 2) + tid;
    const float xbase = (float)(s_base + tid * 4 + 1) * inv;  // thread's pixel 0

    const float4 c0 = sA;                            // one LDS.128
    const float4 c1 = sB;                            // one LDS.128 (w = nseg)

    if (c1.w == 0.0f) {
        // Dominant case (~84%): one segment -> incremental form.
        // v(k) = v0 + k*dv; FFMA with immediate k (rt=1). Added err ~1e-8.
        const float v0 = fmaf(c0.z, xbase - c0.x, c0.y);
        const float dv = c0.z * inv;
        #pragma unroll
        for (int i = 0; i < ITERS; i++) {
            float4 o;
            float* ov = &o.x;
            #pragma unroll
            for (int e = 0; e < 4; e++) {
                ov[e] = fmaf((float)(i * THREADS * 4 + e), dv, v0);
            }
            out4[obase + i * THREADS] = o;
        }
    } else if (c1.w == 1.0f) {
        // One knot boundary: integer threshold kb = first k with xin >= xb,
        // i.e. k >= (xb - xbase)/inv. ceilf of the fast-div ratio; the 1-px
        // ambiguity window of fast math is ~2^-22*S_TOTAL ~ 0.05px -> exact
        // for all practical knots; per-pixel select then needs no float cmp.
        const float v0l = fmaf(c0.z, xbase - c0.x, c0.y);
        const float dvl = c0.z * inv;
        const float v0h = fmaf(c1.z, xbase - c1.x, c1.y);
        const float dvh = c1.z * inv;
        const float kbf = (c1.x - xbase) * (float)S_TOTAL;
        const int   kb  = (int)ceilf(kbf);
        #pragma unroll
        for (int i = 0; i < ITERS; i++) {
            float4 o;
            float* ov = &o.x;
            #pragma unroll
            for (int e = 0; e < 4; e++) {
                const int   ki = i * THREADS * 4 + e;
                const float k  = (float)ki;
                float vl = fmaf(k, dvl, v0l);
                float vh = fmaf(k, dvh, v0h);
                ov[e] = (ki >= kb) ? vh : vl;
            }
            out4[obase + i * THREADS] = o;
        }
    } else {
        // Rare: multiple knots in block -> per-pixel binary search in smem.
        #pragma unroll
        for (int i = 0; i < ITERS; i++) {
            float4 o;
            float* ov = &o.x;
            #pragma unroll
            for (int e = 0; e < 4; e++) {
                float xin = xbase + (float)(i * THREADS * 4 + e) * inv;
                int j = 0;
                #pragma unroll
                for (int st = 16; st >= 1; st >>= 1) {
                    if (scf[j + st].x <= xin) j += st;
                }
                float4 c = scf[j];
                ov[e] = fmaf(c.z, xin - c.x, c.y);
            }
            out4[obase + i * THREADS] = o;
        }
    }
}

extern "C" void kernel_launch(void* const* d_in, const int* in_sizes, int n_in,
                              void* d_out, int out_size) {
    const float* segx = (const float*)d_in[0];
    const float* segy = (const float*)d_in[1];
    float* out = (float*)d_out;

    const int blocks = NB * BLOCKS_PER_BATCH;        // 768
    decoder_pwl_kernel<<<blocks, THREADS>>>(segx, segy, out);
}